// round 4
// baseline (speedup 1.0000x reference)
#include <cuda_runtime.h>
#include <math.h>

#define MAXN 400000
#define MAXE 6400000
#define MAXG 1024
#define EMB  12

// ---------------- static scratch ----------------
__device__ int   g_deg [MAXN];        // real in-edge count (no self loop)
__device__ float g_dinv[MAXN];        // rsqrt(deg+1)
__device__ int   g_off [MAXN];
__device__ int   g_cur [MAXN];
__device__ unsigned long long g_tilestat[512];
__device__ int2  g_epack[MAXE];       // (src row, __float_as_int(norm))
__device__ float g_ha  [(size_t)MAXN*16];
__device__ float g_hb  [(size_t)MAXN*16];
__device__ float g_gsum[MAXG*EMB];
__device__ float g_gmax[MAXG*EMB];
__device__ float g_cnt [MAXG];

__device__ __forceinline__ void atomicMaxF(float* addr, float v) {
    int vi = __float_as_int(v);
    if (vi >= 0) atomicMax((int*)addr, vi);
    else         atomicMin((unsigned int*)addr, __float_as_uint(v));
}

// ---------------- structure passes ----------------
__global__ void k_deg(const int* __restrict__ colp, int E) {
    int e = blockIdx.x * blockDim.x + threadIdx.x;
    if (e < E) atomicAdd(&g_deg[colp[e]], 1);     // no return use -> REDG
}

// decoupled-lookback scan of deg; also dinv and gmax init
__global__ void k_scan(int N, int GE) {
    __shared__ int sh[1024];
    __shared__ int s_prefix;
    int t = threadIdx.x;
    int b = blockIdx.x;
    int i = b * 1024 + t;

    if (i < GE) g_gmax[i] = __int_as_float(0xFF800000);   // -inf

    int deg = (i < N) ? g_deg[i] : 0;
    if (i < N) g_dinv[i] = rsqrtf((float)(deg + 1));
    int v = (i < N) ? deg : 0;

    sh[t] = v; __syncthreads();
    for (int o = 1; o < 1024; o <<= 1) {
        int x = (t >= o) ? sh[t - o] : 0; __syncthreads();
        sh[t] += x; __syncthreads();
    }
    int incl  = sh[t];
    int total = sh[1023];

    if (t == 0) {
        volatile unsigned long long* ts = (volatile unsigned long long*)g_tilestat;
        int pfx = 0;
        if (b > 0) {
            ts[b] = (1ULL << 62) | (unsigned)total;
            int p = b - 1;
            for (;;) {
                unsigned long long st = ts[p];
                unsigned s2 = (unsigned)(st >> 62);
                if (s2 == 0u) continue;
                pfx += (int)(unsigned)(st & 0xffffffffULL);
                if (s2 == 2u) break;
                --p;
            }
        }
        ts[b] = (2ULL << 62) | (unsigned)(pfx + total);
        s_prefix = pfx;
    }
    __syncthreads();
    if (i < N) {
        int off = s_prefix + incl - v;
        g_off[i] = off;
        g_cur[i] = off;
    }
}

// 4 edges per thread: overlap the 318-cyc ATOMG return latencies
__global__ void k_build(const int* __restrict__ rowp,
                        const int* __restrict__ colp, int E) {
    int base = (blockIdx.x * blockDim.x + threadIdx.x) * 4;
    if (base >= E) return;
    int n = min(4, E - base);

    int r[4], c[4], pos[4];
    float dr[4], dc[4];
    #pragma unroll
    for (int k = 0; k < 4; k++) if (k < n) { r[k] = __ldg(&rowp[base+k]); c[k] = __ldg(&colp[base+k]); }
    #pragma unroll
    for (int k = 0; k < 4; k++) if (k < n) pos[k] = atomicAdd(&g_cur[c[k]], 1);
    #pragma unroll
    for (int k = 0; k < 4; k++) if (k < n) { dr[k] = g_dinv[r[k]]; dc[k] = g_dinv[c[k]]; }
    #pragma unroll
    for (int k = 0; k < 4; k++) if (k < n)
        g_epack[pos[k]] = make_int2(r[k], __float_as_int(dr[k] * dc[k]));
}

// ---------------- GCN layer: half-warp per node, feature per lane, no shfl gather ----
template<int FIN, int INSTRIDE>
__global__ void __launch_bounds__(256) k_layer(
        const float* __restrict__ hin, float* __restrict__ hout,
        const float* __restrict__ W, const float* __restrict__ b, int N) {
    __shared__ float sW[FIN * EMB];
    __shared__ float sB[EMB];
    for (int t = threadIdx.x; t < FIN * EMB; t += blockDim.x) sW[t] = W[t];
    if (threadIdx.x < EMB) sB[threadIdx.x] = b[threadIdx.x];
    __syncthreads();

    int hw     = threadIdx.x >> 4;
    int lane16 = threadIdx.x & 15;
    unsigned hmask = 0xFFFFu << (((threadIdx.x & 31) >> 4) << 4);

    int i = blockIdx.x * 16 + hw;
    if (i >= N) return;

    float di = g_dinv[i];
    float sn = di * di;
    float acc = (lane16 < FIN) ? sn * __ldg(&hin[(size_t)i * INSTRIDE + lane16]) : 0.f;
    float s   = sn;

    int beg = g_off[i];
    int cnt = g_deg[i];
    const int2* ep = g_epack + beg;

    int j = 0;
    for (; j + 16 <= cnt; j += 16) {
        int2 e[16];
        #pragma unroll
        for (int q = 0; q < 16; q++) e[q] = __ldg(&ep[j + q]);   // same line, L1 broadcast
        float hv[16];
        #pragma unroll
        for (int q = 0; q < 16; q++)
            hv[q] = (lane16 < FIN) ? __ldg(&hin[(size_t)e[q].x * INSTRIDE + lane16]) : 0.f;
        #pragma unroll
        for (int q = 0; q < 16; q++) {
            float nm = __int_as_float(e[q].y);
            s += nm;
            acc = fmaf(nm, hv[q], acc);
        }
    }
    int rem = cnt - j;
    if (rem > 0) {
        #pragma unroll
        for (int q = 0; q < 16; q++) {
            if (q < rem) {                         // uniform per half-warp
                int2 e = __ldg(&ep[j + q]);
                float nm = __int_as_float(e.y);
                float hv = (lane16 < FIN) ? __ldg(&hin[(size_t)e.x * INSTRIDE + lane16]) : 0.f;
                s += nm;
                acc = fmaf(nm, hv, acc);
            }
        }
    }

    // dense GEMV across the half-warp (epilogue, once per node)
    int k = (lane16 < EMB) ? lane16 : 0;
    float o = s * sB[k];
    #pragma unroll
    for (int f = 0; f < FIN; f++) {
        float af = __shfl_sync(hmask, acc, f, 16);
        o = fmaf(af, sW[f * EMB + k], o);
    }
    float res = (lane16 < EMB) ? tanhf(o) : 0.f;
    hout[(size_t)i * 16 + lane16] = res;
}

// ---------------- pooling (warp-aggregated atomics) ----------------
__global__ void k_pool(const float* __restrict__ h,
                       const int* __restrict__ batch, int N) {
    int i = blockIdx.x * blockDim.x + threadIdx.x;
    bool act = i < N;
    int g = act ? batch[i] : -1;
    float v[EMB];
    if (act) {
        const float4* hp = (const float4*)(h + (size_t)i * 16);
        float4 a = hp[0], bq = hp[1], c = hp[2];
        v[0]=a.x; v[1]=a.y; v[2]=a.z; v[3]=a.w;
        v[4]=bq.x; v[5]=bq.y; v[6]=bq.z; v[7]=bq.w;
        v[8]=c.x; v[9]=c.y; v[10]=c.z; v[11]=c.w;
    } else {
        #pragma unroll
        for (int f = 0; f < EMB; f++) v[f] = 0.f;
    }
    unsigned full = 0xFFFFFFFFu;
    int g0 = __shfl_sync(full, g, 0);
    bool uni = __all_sync(full, g == g0);
    int lane = threadIdx.x & 31;

    if (uni && g0 >= 0) {
        float sm[EMB], mx[EMB];
        #pragma unroll
        for (int f = 0; f < EMB; f++) { sm[f] = v[f]; mx[f] = v[f]; }
        #pragma unroll
        for (int o = 16; o > 0; o >>= 1) {
            #pragma unroll
            for (int f = 0; f < EMB; f++) {
                sm[f] += __shfl_down_sync(full, sm[f], o);
                mx[f] = fmaxf(mx[f], __shfl_down_sync(full, mx[f], o));
            }
        }
        if (lane == 0) {
            #pragma unroll
            for (int f = 0; f < EMB; f++) {
                atomicAdd(&g_gsum[g0 * EMB + f], sm[f]);
                atomicMaxF(&g_gmax[g0 * EMB + f], mx[f]);
            }
            atomicAdd(&g_cnt[g0], 32.f);
        }
    } else if (act) {
        #pragma unroll
        for (int f = 0; f < EMB; f++) {
            atomicAdd(&g_gsum[g * EMB + f], v[f]);
            atomicMaxF(&g_gmax[g * EMB + f], v[f]);
        }
        atomicAdd(&g_cnt[g], 1.f);
    }
}

// ---------------- head ----------------
__global__ void k_final(const float* __restrict__ Wout, const float* __restrict__ bout,
                        float* __restrict__ out, int G) {
    int g = blockIdx.x;
    int t = threadIdx.x;
    __shared__ float hid[2 * EMB];
    if (t < 2 * EMB) {
        float v;
        if (t < EMB) v = g_gmax[g * EMB + t];
        else         v = g_gsum[g * EMB + (t - EMB)] / fmaxf(g_cnt[g], 1.f);
        hid[t] = v;
        out[(size_t)G * 17 + (size_t)g * 24 + t] = v;
    }
    __syncthreads();
    if (t < 17) {
        float o = bout[t];
        #pragma unroll
        for (int f = 0; f < 2 * EMB; f++) o += hid[f] * Wout[f * 17 + t];
        out[(size_t)g * 17 + t] = o;
    }
}

// ---------------- launch ----------------
extern "C" void kernel_launch(void* const* d_in, const int* in_sizes, int n_in,
                              void* d_out, int out_size) {
    const float* x     = (const float*)d_in[0];
    const int*   eidx  = (const int*)  d_in[1];
    const int*   batch = (const int*)  d_in[2];
    const float* W0 = (const float*)d_in[3],  *b0 = (const float*)d_in[4];
    const float* W1 = (const float*)d_in[5],  *b1 = (const float*)d_in[6];
    const float* W2 = (const float*)d_in[7],  *b2 = (const float*)d_in[8];
    const float* W3 = (const float*)d_in[9],  *b3 = (const float*)d_in[10];
    const float* Wo = (const float*)d_in[11], *bo = (const float*)d_in[12];
    float* out = (float*)d_out;

    const int N = in_sizes[0] / 4;
    const int E = in_sizes[1] / 2;
    const int G = out_size / 41;

    const int* rowp = eidx;
    const int* colp = eidx + E;

    // zero scratch via memset nodes (no kernel slots, graph-capturable)
    void *pDeg, *pGsum, *pCnt;
    cudaGetSymbolAddress(&pDeg,  g_deg);
    cudaGetSymbolAddress(&pGsum, g_gsum);
    cudaGetSymbolAddress(&pCnt,  g_cnt);
    cudaMemsetAsync(pDeg,  0, (size_t)N * sizeof(int), 0);
    cudaMemsetAsync(pGsum, 0, (size_t)G * EMB * sizeof(float), 0);
    cudaMemsetAsync(pCnt,  0, (size_t)G * sizeof(float), 0);

    const int T = 256;
    int nbN   = (N + T - 1) / T;
    int nbE   = (E + T - 1) / T;
    int nbE4  = (E + T * 4 - 1) / (T * 4);
    int nScan = (N + 1023) / 1024;
    int nbL   = (N + 15) / 16;

    k_deg<<<nbE, T>>>(colp, E);                               // 0
    k_scan<<<nScan, 1024>>>(N, G * EMB);                      // 1
    k_build<<<nbE4, T>>>(rowp, colp, E);                      // 2

    k_layer<4, 4>  <<<nbL, T>>>(x,    g_ha, W0, b0, N);       // 3
    k_layer<12,16> <<<nbL, T>>>(g_ha, g_hb, W1, b1, N);       // 4
    k_layer<12,16> <<<nbL, T>>>(g_hb, g_ha, W2, b2, N);       // 5
    k_layer<12,16> <<<nbL, T>>>(g_ha, g_hb, W3, b3, N);       // 6

    k_pool<<<nbN, T>>>(g_hb, batch, N);                       // 7
    k_final<<<G, 32>>>(Wo, bo, out, G);                       // 8
}

// round 7
// speedup vs baseline: 1.4307x; 1.4307x over previous
#include <cuda_runtime.h>
#include <math.h>

#define MAXN 400000
#define MAXE 6400000
#define MAXG 1024
#define EMB  12

// ---------------- static scratch ----------------
__device__ int   g_deg [MAXN];        // includes self loop (init 1)
__device__ float g_dinv[MAXN];
__device__ int   g_off [MAXN];
__device__ int   g_cur [MAXN];
__device__ unsigned long long g_tilestat[512];
__device__ int2  g_epack[MAXE];       // (src row, __float_as_int(norm))
__device__ float g_ha  [(size_t)MAXN*16];
__device__ float g_hb  [(size_t)MAXN*16];
__device__ float g_gsum[MAXG*EMB];
__device__ float g_gmax[MAXG*EMB];
__device__ float g_cnt [MAXG];

__device__ __forceinline__ void atomicMaxF(float* addr, float v) {
    int vi = __float_as_int(v);
    if (vi >= 0) atomicMax((int*)addr, vi);
    else         atomicMin((unsigned int*)addr, __float_as_uint(v));
}

// ---------------- structure passes ----------------
__global__ void k_init(int N, int G) {
    int i = blockIdx.x * blockDim.x + threadIdx.x;
    if (i < N) g_deg[i] = 1;                               // self loop
    if (i < 512) g_tilestat[i] = 0ULL;
    if (i < G * EMB) { g_gsum[i] = 0.f; g_gmax[i] = __int_as_float(0xFF800000); }
    if (i < G) g_cnt[i] = 0.f;
}

// 4 edges per thread: overlap REDG issue
__global__ void k_deg(const int* __restrict__ colp, int E) {
    int base = (blockIdx.x * blockDim.x + threadIdx.x) * 4;
    if (base >= E) return;
    int n = min(4, E - base);
    int c[4];
    #pragma unroll
    for (int k = 0; k < 4; k++) if (k < n) c[k] = __ldg(&colp[base + k]);
    #pragma unroll
    for (int k = 0; k < 4; k++) if (k < n) atomicAdd(&g_deg[c[k]], 1);
}

// single-pass decoupled-lookback scan of (deg-1); also computes dinv.
__global__ void k_scan(int N) {
    __shared__ int sh[1024];
    __shared__ int s_prefix;
    int t = threadIdx.x;
    int b = blockIdx.x;
    int i = b * 1024 + t;

    int deg = (i < N) ? g_deg[i] : 1;
    if (i < N) g_dinv[i] = rsqrtf((float)deg);
    int v = (i < N) ? (deg - 1) : 0;

    sh[t] = v; __syncthreads();
    for (int o = 1; o < 1024; o <<= 1) {
        int x = (t >= o) ? sh[t - o] : 0; __syncthreads();
        sh[t] += x; __syncthreads();
    }
    int incl  = sh[t];
    int total = sh[1023];

    if (t == 0) {
        volatile unsigned long long* ts = (volatile unsigned long long*)g_tilestat;
        int pfx = 0;
        if (b > 0) {
            ts[b] = (1ULL << 62) | (unsigned)total;      // publish aggregate
            int p = b - 1;
            for (;;) {
                unsigned long long st = ts[p];
                unsigned s2 = (unsigned)(st >> 62);
                if (s2 == 0u) continue;
                pfx += (int)(unsigned)(st & 0xffffffffULL);
                if (s2 == 2u) break;
                --p;
            }
        }
        ts[b] = (2ULL << 62) | (unsigned)(pfx + total);  // publish inclusive prefix
        s_prefix = pfx;
    }
    __syncthreads();
    if (i < N) {
        int off = s_prefix + incl - v;
        g_off[i] = off;
        g_cur[i] = off;
    }
}

// 4 edges per thread: overlap ATOMG return latencies
__global__ void k_build(const int* __restrict__ rowp,
                        const int* __restrict__ colp, int E) {
    int base = (blockIdx.x * blockDim.x + threadIdx.x) * 4;
    if (base >= E) return;
    int n = min(4, E - base);

    int r[4], c[4], pos[4];
    float dr[4], dc[4];
    #pragma unroll
    for (int k = 0; k < 4; k++) if (k < n) { r[k] = __ldg(&rowp[base+k]); c[k] = __ldg(&colp[base+k]); }
    #pragma unroll
    for (int k = 0; k < 4; k++) if (k < n) pos[k] = atomicAdd(&g_cur[c[k]], 1);
    #pragma unroll
    for (int k = 0; k < 4; k++) if (k < n) { dr[k] = g_dinv[r[k]]; dc[k] = g_dinv[c[k]]; }
    #pragma unroll
    for (int k = 0; k < 4; k++) if (k < n)
        g_epack[pos[k]] = make_int2(r[k], __float_as_int(dr[k] * dc[k]));
}

// ---------------- GCN layer: half-warp per node, feature per lane ----------------
// out[i,k] = tanh( sum_f acc[f]*W[f,k] + s*b[k] ),  acc[f] = sum_src norm*h[src,f]
template<int FIN, int INSTRIDE>
__global__ void __launch_bounds__(256) k_layer(
        const float* __restrict__ hin, float* __restrict__ hout,
        const float* __restrict__ W, const float* __restrict__ b, int N) {
    __shared__ float sW[FIN * EMB];
    __shared__ float sB[EMB];
    for (int t = threadIdx.x; t < FIN * EMB; t += blockDim.x) sW[t] = W[t];
    if (threadIdx.x < EMB) sB[threadIdx.x] = b[threadIdx.x];
    __syncthreads();

    int hw     = threadIdx.x >> 4;          // half-warp slot 0..15
    int lane16 = threadIdx.x & 15;          // feature lane
    unsigned hmask = 0xFFFFu << (((threadIdx.x & 31) >> 4) << 4);

    int i = blockIdx.x * 16 + hw;
    if (i >= N) return;

    float di = g_dinv[i];
    float sn = di * di;
    float acc = (lane16 < FIN) ? sn * __ldg(&hin[(size_t)i * INSTRIDE + lane16]) : 0.f;
    float s   = sn;

    int beg = g_off[i];
    int cnt = g_deg[i] - 1;
    const int2* ep = g_epack + beg;

    int j0 = 0;
    for (; j0 + 16 <= cnt; j0 += 16) {
        int2 e = __ldg(&ep[j0 + lane16]);           // coalesced 128B per half-warp
        #pragma unroll
        for (int q = 0; q < 16; q++) {
            int   r  = __shfl_sync(hmask, e.x, q, 16);
            float nm = __int_as_float(__shfl_sync(hmask, e.y, q, 16));
            s += nm;
            float hv = (lane16 < FIN) ? __ldg(&hin[(size_t)r * INSTRIDE + lane16]) : 0.f;
            acc = fmaf(nm, hv, acc);
        }
    }
    int rem = cnt - j0;
    if (rem > 0) {
        int2 e = (lane16 < rem) ? __ldg(&ep[j0 + lane16]) : make_int2(0, 0);
        for (int q = 0; q < rem; q++) {
            int   r  = __shfl_sync(hmask, e.x, q, 16);
            float nm = __int_as_float(__shfl_sync(hmask, e.y, q, 16));
            s += nm;
            float hv = (lane16 < FIN) ? __ldg(&hin[(size_t)r * INSTRIDE + lane16]) : 0.f;
            acc = fmaf(nm, hv, acc);
        }
    }

    // dense GEMV across the half-warp
    int k = (lane16 < EMB) ? lane16 : 0;
    float o = s * sB[k];
    #pragma unroll
    for (int f = 0; f < FIN; f++) {
        float af = __shfl_sync(hmask, acc, f, 16);
        o = fmaf(af, sW[f * EMB + k], o);
    }
    float res = (lane16 < EMB) ? tanhf(o) : 0.f;
    hout[(size_t)i * 16 + lane16] = res;            // coalesced 64B per node
}

// ---------------- pooling (warp-aggregated atomics) ----------------
__global__ void k_pool(const float* __restrict__ h,
                       const int* __restrict__ batch, int N) {
    int i = blockIdx.x * blockDim.x + threadIdx.x;
    bool act = i < N;
    int g = act ? batch[i] : -1;
    float v[EMB];
    if (act) {
        const float4* hp = (const float4*)(h + (size_t)i * 16);
        float4 a = hp[0], bq = hp[1], c = hp[2];
        v[0]=a.x; v[1]=a.y; v[2]=a.z; v[3]=a.w;
        v[4]=bq.x; v[5]=bq.y; v[6]=bq.z; v[7]=bq.w;
        v[8]=c.x; v[9]=c.y; v[10]=c.z; v[11]=c.w;
    } else {
        #pragma unroll
        for (int f = 0; f < EMB; f++) v[f] = 0.f;
    }
    unsigned full = 0xFFFFFFFFu;
    int g0 = __shfl_sync(full, g, 0);
    bool uni = __all_sync(full, g == g0);
    int lane = threadIdx.x & 31;

    if (uni && g0 >= 0) {
        float sm[EMB], mx[EMB];
        #pragma unroll
        for (int f = 0; f < EMB; f++) { sm[f] = v[f]; mx[f] = v[f]; }
        #pragma unroll
        for (int o = 16; o > 0; o >>= 1) {
            #pragma unroll
            for (int f = 0; f < EMB; f++) {
                sm[f] += __shfl_down_sync(full, sm[f], o);
                mx[f] = fmaxf(mx[f], __shfl_down_sync(full, mx[f], o));
            }
        }
        if (lane == 0) {
            #pragma unroll
            for (int f = 0; f < EMB; f++) {
                atomicAdd(&g_gsum[g0 * EMB + f], sm[f]);
                atomicMaxF(&g_gmax[g0 * EMB + f], mx[f]);
            }
            atomicAdd(&g_cnt[g0], 32.f);
        }
    } else if (act) {
        #pragma unroll
        for (int f = 0; f < EMB; f++) {
            atomicAdd(&g_gsum[g * EMB + f], v[f]);
            atomicMaxF(&g_gmax[g * EMB + f], v[f]);
        }
        atomicAdd(&g_cnt[g], 1.f);
    }
}

// ---------------- head: hidden = [gmax, gmean]; out = hidden@Wout + bout ----
__global__ void k_final(const float* __restrict__ Wout, const float* __restrict__ bout,
                        float* __restrict__ out, int G) {
    int g = blockIdx.x;
    int t = threadIdx.x;
    __shared__ float hid[2 * EMB];
    if (t < 2 * EMB) {
        float v;
        if (t < EMB) v = g_gmax[g * EMB + t];
        else         v = g_gsum[g * EMB + (t - EMB)] / fmaxf(g_cnt[g], 1.f);
        hid[t] = v;
        out[(size_t)G * 17 + (size_t)g * 24 + t] = v;   // hidden block
    }
    __syncthreads();
    if (t < 17) {
        float o = bout[t];
        #pragma unroll
        for (int f = 0; f < 2 * EMB; f++) o += hid[f] * Wout[f * 17 + t];
        out[(size_t)g * 17 + t] = o;                    // out block
    }
}

// ---------------- launch ----------------
extern "C" void kernel_launch(void* const* d_in, const int* in_sizes, int n_in,
                              void* d_out, int out_size) {
    const float* x     = (const float*)d_in[0];
    const int*   eidx  = (const int*)  d_in[1];
    const int*   batch = (const int*)  d_in[2];
    const float* W0 = (const float*)d_in[3],  *b0 = (const float*)d_in[4];
    const float* W1 = (const float*)d_in[5],  *b1 = (const float*)d_in[6];
    const float* W2 = (const float*)d_in[7],  *b2 = (const float*)d_in[8];
    const float* W3 = (const float*)d_in[9],  *b3 = (const float*)d_in[10];
    const float* Wo = (const float*)d_in[11], *bo = (const float*)d_in[12];
    float* out = (float*)d_out;

    const int N = in_sizes[0] / 4;
    const int E = in_sizes[1] / 2;
    const int G = out_size / 41;           // 17 + 24 per graph

    const int* rowp = eidx;
    const int* colp = eidx + E;

    const int T = 256;
    int nbN   = (N + T - 1) / T;
    int nbE4  = (E + T * 4 - 1) / (T * 4);
    int nScan = (N + 1023) / 1024;
    int nbL   = (N + 15) / 16;             // 16 nodes per 256-thread block

    k_init<<<nbN, T>>>(N, G);                             // 0
    k_deg<<<nbE4, T>>>(colp, E);                          // 1
    k_scan<<<nScan, 1024>>>(N);                           // 2
    k_build<<<nbE4, T>>>(rowp, colp, E);                  // 3

    k_layer<4, 4>  <<<nbL, T>>>(x,    g_ha, W0, b0, N);   // 4
    k_layer<12,16> <<<nbL, T>>>(g_ha, g_hb, W1, b1, N);   // 5
    k_layer<12,16> <<<nbL, T>>>(g_hb, g_ha, W2, b2, N);   // 6
    k_layer<12,16> <<<nbL, T>>>(g_ha, g_hb, W3, b3, N);   // 7

    k_pool<<<nbN, T>>>(g_hb, batch, N);                   // 8
    k_final<<<G, 32>>>(Wo, bo, out, G);                   // 9
}